// round 13
// baseline (speedup 1.0000x reference)
#include <cuda_runtime.h>
#include <cstdint>

#define NB 4
#define NV 20000
#define NP 400000
#define NNETS 50000
#define MPINS 32
#define GRID 64

#define NKC 8           // nets per smem stage (per buffer)
#define NGRP 296        // k_cong blocks = net groups (2 CTAs/SM)
#define NPER 176        // padded nets per group (22 chunks of 8)
#define NNP (NGRP * NPER)   // 52096 padded nets
#define PPB ((NP + 255) / 256)   // 1563 pinpos blocks

// -------- static scratch (no allocation allowed) --------
__device__ float  d_pin_pos[NP * 8];            // [P][B][2] -> 2x float4 per pin
__device__ float  d_bbox[NNP * NB * 4];         // per (net,batch): xmin,xmax,ymin,ymax (grid units)
__device__ float  d_part[NGRP * NB * GRID * GRID];  // per-group rudy partials (19.4 MB)
__device__ float  d_rudy[NB * GRID * GRID];
__device__ double d_hpwl[NB];

// ---------------- pin positions (+ folded init in tail blocks) -------------
__global__ __launch_bounds__(256) void k_pinpos(
    const float* __restrict__ pos,   // (B,V,2)
    const float* __restrict__ roh,   // (B,V,4)
    const int*   __restrict__ p2m,   // (P,)
    const float* __restrict__ poff)  // (P,2)
{
    if (blockIdx.x >= PPB) {   // init tail: sentinels for padded nets + hpwl zero
        int t = (blockIdx.x - PPB) * 256 + threadIdx.x;
        if (t < (NNP - NNETS) * NB)   // sentinel -> denom=inf -> window == 0
            ((float4*)d_bbox)[NNETS * NB + t] = make_float4(2000.f, -2000.f, 2000.f, -2000.f);
        if (t < NB) d_hpwl[t] = 0.0;
        return;
    }
    int p = blockIdx.x * blockDim.x + threadIdx.x;
    if (p >= NP) return;
    int m = p2m[p];
    float2 off = ((const float2*)poff)[p];
    float o[8];
#pragma unroll
    for (int b = 0; b < NB; b++) {
        float2 mp = __ldg((const float2*)pos + b * NV + m);
        float4 oh = __ldg((const float4*)roh + b * NV + m);
        float c = oh.x - oh.z;  // rotations 0..3 collapse to cos/sin in {-1,0,1}
        float s = oh.y - oh.w;
        o[2 * b + 0] = mp.x + c * off.x - s * off.y;
        o[2 * b + 1] = mp.y + s * off.x + c * off.y;
    }
    float4* dst = (float4*)d_pin_pos + p * 2;
    dst[0] = make_float4(o[0], o[1], o[2], o[3]);
    dst[1] = make_float4(o[4], o[5], o[6], o[7]);
}

// ---------------- per-net LSE wirelength + bbox ----------------
// 4 nets per warp: 8 lanes per net, 4 pin slots per lane.
// BRANCHLESS: all 8 pin gathers issued upfront (MLP=8/lane), invalid slots
// masked via selects / mask-multiply (contribute exactly 0 / +-1e9).
__global__ __launch_bounds__(256) void k_net(
    const int*   __restrict__ n2p,   // (NN,32)
    const float* __restrict__ nw)    // (NN,)
{
    int warpG = (blockIdx.x * blockDim.x + threadIdx.x) >> 5;
    int lane  = threadIdx.x & 31;
    int grp   = lane >> 3;           // net slot within warp (0..3)
    int r     = lane & 7;            // lane within group
    int net   = warpG * 4 + grp;
    bool act  = (net < NNETS);
    int netc  = act ? net : 0;

    // batched index + pin loads (no branches around memory)
    int4 idx4 = __ldg((const int4*)n2p + netc * 8 + r);
    int   idxs[4] = {idx4.x, idx4.y, idx4.z, idx4.w};
    float msk[4];
    float4 lo4[4], hi4[4];
#pragma unroll
    for (int s = 0; s < 4; s++) {
        bool v  = idxs[s] >= 0;
        msk[s]  = v ? 1.f : 0.f;
        int q   = v ? idxs[s] : 0;
        const float4* pp = (const float4*)d_pin_pos + (size_t)q * 2;
        lo4[s] = __ldg(pp);
        hi4[s] = __ldg(pp + 1);
    }

    float mx[NB][2], mn[NB][2], s1[NB][2], s2[NB][2];
#pragma unroll
    for (int b = 0; b < NB; b++)
#pragma unroll
        for (int a = 0; a < 2; a++) {
            mx[b][a] = -1e9f; mn[b][a] = 1e9f;
            s1[b][a] = 0.f;   s2[b][a] = 0.f;
        }

#pragma unroll
    for (int s = 0; s < 4; s++) {
        float m = msk[s];
        float v[NB][2] = {{lo4[s].x, lo4[s].y}, {lo4[s].z, lo4[s].w},
                          {hi4[s].x, hi4[s].y}, {hi4[s].z, hi4[s].w}};
#pragma unroll
        for (int b = 0; b < NB; b++)
#pragma unroll
            for (int a = 0; a < 2; a++) {
                float val = v[b][a];
                float vmx = (m != 0.f) ? val : -1e9f;
                float vmn = (m != 0.f) ? val :  1e9f;
                mx[b][a] = fmaxf(mx[b][a], vmx);
                mn[b][a] = fminf(mn[b][a], vmn);
                // masked slots contribute exactly 0; |v|<=1 -> bounded
                s1[b][a] += m * __expf( 10.f * val);
                s2[b][a] += m * __expf(-10.f * val);
            }
    }

    // 3-step butterfly within each 8-lane group (xor 4,2,1 stay in-group)
#pragma unroll
    for (int o = 4; o > 0; o >>= 1) {
#pragma unroll
        for (int b = 0; b < NB; b++)
#pragma unroll
            for (int a = 0; a < 2; a++) {
                mx[b][a] = fmaxf(mx[b][a], __shfl_xor_sync(0xffffffffu, mx[b][a], o));
                mn[b][a] = fminf(mn[b][a], __shfl_xor_sync(0xffffffffu, mn[b][a], o));
                s1[b][a] += __shfl_xor_sync(0xffffffffu, s1[b][a], o);
                s2[b][a] += __shfl_xor_sync(0xffffffffu, s2[b][a], o);
            }
    }

    float wl[NB] = {0.f, 0.f, 0.f, 0.f};
    if (r == 0 && act) {
        float w = __ldg(&nw[net]);
#pragma unroll
        for (int b = 0; b < NB; b++) {
            // (lse_max - lse_min) over both axes == 0.1 * log(S1x*S2x*S1y*S2y)
            float prod = (s1[b][0] * s2[b][0]) * (s1[b][1] * s2[b][1]);
            wl[b] = w * 0.1f * __logf(prod);
            float4 bb;
            bb.x = (mn[b][0] + 1.f) * 31.5f;   // (M-1)/2
            bb.y = (mx[b][0] + 1.f) * 31.5f;
            bb.z = (mn[b][1] + 1.f) * 31.5f;
            bb.w = (mx[b][1] + 1.f) * 31.5f;
            ((float4*)d_bbox)[net * NB + b] = bb;
        }
    }
#pragma unroll
    for (int b = 0; b < NB; b++) {
        wl[b] += __shfl_xor_sync(0xffffffffu, wl[b], 8);
        wl[b] += __shfl_xor_sync(0xffffffffu, wl[b], 16);
    }

    __shared__ double s_h[NB];
    if (threadIdx.x < NB) s_h[threadIdx.x] = 0.0;
    __syncthreads();
    if (lane == 0) {
#pragma unroll
        for (int b = 0; b < NB; b++) atomicAdd(&s_h[b], (double)wl[b]);
    }
    __syncthreads();
    if (threadIdx.x < NB) atomicAdd(&d_hpwl[threadIdx.x], s_h[threadIdx.x]);
}

// ---------------- congestion: split-K rank-1 accumulation GEMM ----------------
// Block = one padded net-group (176 nets, 22 chunks of 8), all 4 batches
// (64 threads each), thread tile 8x8 (1.0 B/FMA). Ping-pong smem + MANUAL
// register prefetch: k+1's 4 float4 loads issue before k's 32 FFMA2, hiding
// the 29-cyc LDS latency and overlapping the LDS floor with the FMA floor.
union F4U { float4 f; unsigned long long u[2]; };

__device__ __forceinline__ void cong_fill(
    float (&s_x)[2][NB][NKC][GRID], float (&s_y)[2][NB][NKC][GRID],
    int buf, int base, int tid)
{
#pragma unroll
    for (int it0 = 0; it0 < 2; it0++) {          // NKC*64 = 512 items / 256 thr
        int it  = it0 * 256 + tid;
        int k   = it >> 6;
        int bi  = (it >> 4) & 3;
        int sub = it & 15;
        int a   = sub >> 3;          // 0 = x axis, 1 = y axis
        int g0  = (sub & 7) * 8;     // 8 cells per item
        float4 bb = __ldg((const float4*)d_bbox + (base + k) * NB + bi);
        float lmn = a ? bb.z : bb.x;
        float lmx = a ? bb.w : bb.y;
        float u   = __expf(2.f * (lmn - (float)g0) - 1.f);
        float vv  = __expf(2.f * ((float)g0 - lmx) - 1.f);
        float Cc  = __expf(-2.f * (lmx - lmn + 1.f));
        float base1 = 1.f + Cc;
        float scale = 1.f;
        if (a) {
            float bs = fmaxf((bb.y - bb.x + 1.f) * (bb.w - bb.z + 1.f), 1.f);
            scale = __fdividef(1.f, bs);
        }
        float* dst = a ? &s_y[buf][bi][k][g0] : &s_x[buf][bi][k][g0];
#pragma unroll
        for (int g = 0; g < 8; g++) {
            dst[g] = __fdividef(scale, base1 + u + vv);  // sigmoid product (y: /bbox_size)
            u  *= 0.13533528323661270f;                  // e^-2
            vv *= 7.3890560989306495f;                   // e^+2
        }
    }
}

__global__ __launch_bounds__(256, 2) void k_cong() {
    __shared__ float s_x[2][NB][NKC][GRID];     // 16 KB
    __shared__ float s_y[2][NB][NKC][GRID];     // 16 KB
    int tid   = threadIdx.x;
    int group = blockIdx.x;
    int b     = tid >> 6;           // batch (0..3)
    int t64   = tid & 63;
    int j0    = (t64 & 7) * 8;      // x-columns
    int i0    = (t64 >> 3) * 8;     // y-rows
    int n0    = group * NPER;

    unsigned long long acc[8][4];   // acc[i][jp]: row i0+i, col pair (j0+2jp, +1)
#pragma unroll
    for (int i = 0; i < 8; i++)
#pragma unroll
        for (int jp = 0; jp < 4; jp++) acc[i][jp] = 0ull;

    cong_fill(s_x, s_y, 0, n0, tid);
    __syncthreads();

    const int NCHUNK = NPER / NKC;              // 22
    for (int c = 0; c < NCHUNK; c++) {
        int cur = c & 1;
        // software pipeline: prefetch k+1 while FMA'ing k
        F4U cx0, cx1, cy0, cy1;
        cx0.f = *(const float4*)&s_x[cur][b][0][j0];
        cx1.f = *(const float4*)&s_x[cur][b][0][j0 + 4];
        cy0.f = *(const float4*)&s_y[cur][b][0][i0];
        cy1.f = *(const float4*)&s_y[cur][b][0][i0 + 4];
#pragma unroll
        for (int k = 0; k < NKC; k++) {
            F4U nx0, nx1, ny0, ny1;
            if (k + 1 < NKC) {
                nx0.f = *(const float4*)&s_x[cur][b][k + 1][j0];
                nx1.f = *(const float4*)&s_x[cur][b][k + 1][j0 + 4];
                ny0.f = *(const float4*)&s_y[cur][b][k + 1][i0];
                ny1.f = *(const float4*)&s_y[cur][b][k + 1][i0 + 4];
            }
            float yv[8] = {cy0.f.x, cy0.f.y, cy0.f.z, cy0.f.w,
                           cy1.f.x, cy1.f.y, cy1.f.z, cy1.f.w};
#pragma unroll
            for (int i = 0; i < 8; i++) {
                unsigned long long yy;
                asm("mov.b64 %0, {%1, %1};" : "=l"(yy) : "f"(yv[i]));
                asm("fma.rn.f32x2 %0, %1, %2, %0;" : "+l"(acc[i][0]) : "l"(yy), "l"(cx0.u[0]));
                asm("fma.rn.f32x2 %0, %1, %2, %0;" : "+l"(acc[i][1]) : "l"(yy), "l"(cx0.u[1]));
                asm("fma.rn.f32x2 %0, %1, %2, %0;" : "+l"(acc[i][2]) : "l"(yy), "l"(cx1.u[0]));
                asm("fma.rn.f32x2 %0, %1, %2, %0;" : "+l"(acc[i][3]) : "l"(yy), "l"(cx1.u[1]));
            }
            if (k + 1 < NKC) { cx0 = nx0; cx1 = nx1; cy0 = ny0; cy1 = ny1; }
        }
        if (c + 1 < NCHUNK)
            cong_fill(s_x, s_y, cur ^ 1, n0 + (c + 1) * NKC, tid);
        __syncthreads();   // ends chunk: next fill may then overwrite 'cur'
    }

    // atomic-free epilogue: exclusive partial slab per group
    float* dst = &d_part[((size_t)group * NB + b) * (GRID * GRID) + i0 * GRID + j0];
#pragma unroll
    for (int i = 0; i < 8; i++) {
        F4U lo, hi;
        lo.u[0] = acc[i][0]; lo.u[1] = acc[i][1];
        hi.u[0] = acc[i][2]; hi.u[1] = acc[i][3];
        *(float4*)(dst + i * GRID)     = lo.f;
        *(float4*)(dst + i * GRID + 4) = hi.f;
    }
}

// ---------------- reduce group partials -> d_rudy ----------------
// 512 blocks, 8 threads per cell (296 = 8 x 37): 37-deep chains, high MLP.
__global__ __launch_bounds__(256) void k_reduce() {
    int t    = threadIdx.x;
    int cell = blockIdx.x * 32 + (t >> 3);      // 512 blocks x 32 cells
    int part = t & 7;
    const float* p = d_part + cell;
    float s = 0.f;
    int g0 = part * (NGRP / 8);                 // 37 groups per part
#pragma unroll
    for (int g = g0; g < g0 + NGRP / 8; g++) s += p[(size_t)g * (NB * GRID * GRID)];
    s += __shfl_xor_sync(0xffffffffu, s, 1);
    s += __shfl_xor_sync(0xffffffffu, s, 2);
    s += __shfl_xor_sync(0xffffffffu, s, 4);
    if (part == 0) d_rudy[cell] = s;
}

// ---------------- separable Gaussian smooth + overflow penalty + final ----------------
__global__ __launch_bounds__(256) void k_final(float* __restrict__ out) {
    int b = blockIdx.x;
    __shared__ float s_in[GRID][GRID];
    __shared__ float s_tmp[GRID][GRID];
    __shared__ float s_red[256];
    int tid = threadIdx.x;

    float w[7];
    {
        float sum = 0.f;
#pragma unroll
        for (int i = 0; i < 7; i++) {
            float x = (float)(i - 3);
            w[i] = expf(-x * x / 4.5f);   // 2*sigma^2 = 4.5
            sum += w[i];
        }
        float inv = 1.f / sum;
#pragma unroll
        for (int i = 0; i < 7; i++) w[i] *= inv;  // outer(w,w) == normalized 2D kernel
    }

    for (int i = tid; i < GRID * GRID; i += 256)
        s_in[i >> 6][i & 63] = d_rudy[b * GRID * GRID + i];
    __syncthreads();

    for (int i = tid; i < GRID * GRID; i += 256) {
        int r = i >> 6, cx = i & 63;
        float acc = 0.f;
#pragma unroll
        for (int d = -3; d <= 3; d++) {
            int rr = r + d;
            if (rr >= 0 && rr < GRID) acc = fmaf(w[d + 3], s_in[rr][cx], acc);
        }
        s_tmp[r][cx] = acc;
    }
    __syncthreads();

    float pen = 0.f;
    for (int i = tid; i < GRID * GRID; i += 256) {
        int r = i >> 6, cx = i & 63;
        float acc = 0.f;
#pragma unroll
        for (int d = -3; d <= 3; d++) {
            int cc = cx + d;
            if (cc >= 0 && cc < GRID) acc = fmaf(w[d + 3], s_tmp[r][cc], acc);
        }
        float o = acc - 1.f;            // THRESH = 1
        if (o > 0.f) pen = fmaf(o, o, pen);
    }
    s_red[tid] = pen;
    __syncthreads();
    for (int s = 128; s > 0; s >>= 1) {
        if (tid < s) s_red[tid] += s_red[tid + s];
        __syncthreads();
    }
    if (tid == 0)
        out[b] = (float)(d_hpwl[b] + 0.5 * (double)s_red[0]);  // W_WL=1, W_CONG=0.5
}

// ---------------- launcher ----------------
extern "C" void kernel_launch(void* const* d_in, const int* in_sizes, int n_in,
                              void* d_out, int out_size)
{
    const float* positions = nullptr;
    const int*   n2p = nullptr;
    const int*   p2m = nullptr;
    const float* poff = nullptr;
    const float* roh = nullptr;
    const float* nw = nullptr;

    for (int i = 0; i < n_in; i++) {
        switch (in_sizes[i]) {                      // all element counts distinct
            case NB * NV * 2:    positions = (const float*)d_in[i]; break; // 160000
            case NNETS * MPINS:  n2p       = (const int*)  d_in[i]; break; // 1600000
            case NP:             p2m       = (const int*)  d_in[i]; break; // 400000
            case NP * 2:         poff      = (const float*)d_in[i]; break; // 800000
            case NB * NV * 4:    roh       = (const float*)d_in[i]; break; // 320000
            case NNETS:          nw        = (const float*)d_in[i]; break; // 50000
            default: break;
        }
    }
    if (!positions || !n2p || !p2m || !poff || !roh || !nw) return;

    k_pinpos<<<PPB + 33, 256>>>(positions, roh, p2m, poff);   // tail blocks do init
    k_net<<<(NNETS + 31) / 32, 256>>>(n2p, nw);
    k_cong<<<NGRP, 256>>>();
    k_reduce<<<512, 256>>>();
    k_final<<<NB, 256>>>((float*)d_out);
}

// round 14
// speedup vs baseline: 1.5660x; 1.5660x over previous
#include <cuda_runtime.h>
#include <cstdint>

#define NB 4
#define NV 20000
#define NP 400000
#define NNETS 50000
#define MPINS 32
#define GRID 64

#define NKC 8           // nets per smem stage (per buffer)
#define NGRP 296        // k_cong blocks = net groups (2 CTAs/SM)
#define NPER 176        // padded nets per group (22 chunks of 8)
#define NNP (NGRP * NPER)   // 52096 padded nets
#define PPB ((NP + 255) / 256)   // 1563 pinpos blocks

// -------- static scratch (no allocation allowed) --------
__device__ float  d_pin_pos[NP * 8];            // [P][B][2] -> 2x float4 per pin
__device__ float  d_bbox[NNP * NB * 4];         // per (net,batch): xmin,xmax,ymin,ymax (grid units)
__device__ float  d_part[NGRP * NB * GRID * GRID];  // per-group rudy partials (19.4 MB)
__device__ float  d_rudy[NB * GRID * GRID];
__device__ double d_hpwl[NB];

// ---------------- pin positions (+ folded init in tail blocks) -------------
__global__ __launch_bounds__(256) void k_pinpos(
    const float* __restrict__ pos,   // (B,V,2)
    const float* __restrict__ roh,   // (B,V,4)
    const int*   __restrict__ p2m,   // (P,)
    const float* __restrict__ poff)  // (P,2)
{
    if (blockIdx.x >= PPB) {   // init tail: sentinels for padded nets + hpwl zero
        int t = (blockIdx.x - PPB) * 256 + threadIdx.x;
        if (t < (NNP - NNETS) * NB)   // sentinel -> denom=inf -> window == 0
            ((float4*)d_bbox)[NNETS * NB + t] = make_float4(2000.f, -2000.f, 2000.f, -2000.f);
        if (t < NB) d_hpwl[t] = 0.0;
        return;
    }
    int p = blockIdx.x * blockDim.x + threadIdx.x;
    if (p >= NP) return;
    int m = p2m[p];
    float2 off = ((const float2*)poff)[p];
    float o[8];
#pragma unroll
    for (int b = 0; b < NB; b++) {
        float2 mp = __ldg((const float2*)pos + b * NV + m);
        float4 oh = __ldg((const float4*)roh + b * NV + m);
        float c = oh.x - oh.z;  // rotations 0..3 collapse to cos/sin in {-1,0,1}
        float s = oh.y - oh.w;
        o[2 * b + 0] = mp.x + c * off.x - s * off.y;
        o[2 * b + 1] = mp.y + s * off.x + c * off.y;
    }
    float4* dst = (float4*)d_pin_pos + p * 2;
    dst[0] = make_float4(o[0], o[1], o[2], o[3]);
    dst[1] = make_float4(o[4], o[5], o[6], o[7]);
}

// ---------------- per-net LSE wirelength + bbox ----------------
// 4 nets per warp: 8 lanes per net, 4 pin slots per lane.
// REVERTED to guarded-load form (the variant inside the measured-104.5 binary)
// to A/B against the branchless rewrite that coincided with the 164us outlier.
__global__ __launch_bounds__(256) void k_net(
    const int*   __restrict__ n2p,   // (NN,32)
    const float* __restrict__ nw)    // (NN,)
{
    int warpG = (blockIdx.x * blockDim.x + threadIdx.x) >> 5;
    int lane  = threadIdx.x & 31;
    int grp   = lane >> 3;           // net slot within warp (0..3)
    int r     = lane & 7;            // lane within group
    int net   = warpG * 4 + grp;
    bool act  = (net < NNETS);

    float mx[NB][2], mn[NB][2], s1[NB][2], s2[NB][2];
#pragma unroll
    for (int b = 0; b < NB; b++)
#pragma unroll
        for (int a = 0; a < 2; a++) {
            mx[b][a] = -1e9f; mn[b][a] = 1e9f;
            s1[b][a] = 0.f;   s2[b][a] = 0.f;
        }

    if (act) {
        int4 idx4 = __ldg((const int4*)n2p + net * 8 + r);
        int idxs[4] = {idx4.x, idx4.y, idx4.z, idx4.w};
#pragma unroll
        for (int s = 0; s < 4; s++) {
            int idx = idxs[s];
            if (idx >= 0) {
                const float4* pp = (const float4*)d_pin_pos + (size_t)idx * 2;
                float4 lo = __ldg(pp), hi = __ldg(pp + 1);
                float v[NB][2] = {{lo.x, lo.y}, {lo.z, lo.w}, {hi.x, hi.y}, {hi.z, hi.w}};
#pragma unroll
                for (int b = 0; b < NB; b++)
#pragma unroll
                    for (int a = 0; a < 2; a++) {
                        float val = v[b][a];
                        mx[b][a] = fmaxf(mx[b][a], val);
                        mn[b][a] = fminf(mn[b][a], val);
                        // masked slots contribute exactly 0; |v|<=1 -> bounded
                        s1[b][a] += __expf( 10.f * val);
                        s2[b][a] += __expf(-10.f * val);
                    }
            }
        }
    }

    // 3-step butterfly within each 8-lane group (xor 4,2,1 stay in-group)
#pragma unroll
    for (int o = 4; o > 0; o >>= 1) {
#pragma unroll
        for (int b = 0; b < NB; b++)
#pragma unroll
            for (int a = 0; a < 2; a++) {
                mx[b][a] = fmaxf(mx[b][a], __shfl_xor_sync(0xffffffffu, mx[b][a], o));
                mn[b][a] = fminf(mn[b][a], __shfl_xor_sync(0xffffffffu, mn[b][a], o));
                s1[b][a] += __shfl_xor_sync(0xffffffffu, s1[b][a], o);
                s2[b][a] += __shfl_xor_sync(0xffffffffu, s2[b][a], o);
            }
    }

    float wl[NB] = {0.f, 0.f, 0.f, 0.f};
    if (r == 0 && act) {
        float w = __ldg(&nw[net]);
#pragma unroll
        for (int b = 0; b < NB; b++) {
            // (lse_max - lse_min) over both axes == 0.1 * log(S1x*S2x*S1y*S2y)
            float prod = (s1[b][0] * s2[b][0]) * (s1[b][1] * s2[b][1]);
            wl[b] = w * 0.1f * __logf(prod);
            float4 bb;
            bb.x = (mn[b][0] + 1.f) * 31.5f;   // (M-1)/2
            bb.y = (mx[b][0] + 1.f) * 31.5f;
            bb.z = (mn[b][1] + 1.f) * 31.5f;
            bb.w = (mx[b][1] + 1.f) * 31.5f;
            ((float4*)d_bbox)[net * NB + b] = bb;
        }
    }
#pragma unroll
    for (int b = 0; b < NB; b++) {
        wl[b] += __shfl_xor_sync(0xffffffffu, wl[b], 8);
        wl[b] += __shfl_xor_sync(0xffffffffu, wl[b], 16);
    }

    __shared__ double s_h[NB];
    if (threadIdx.x < NB) s_h[threadIdx.x] = 0.0;
    __syncthreads();
    if (lane == 0) {
#pragma unroll
        for (int b = 0; b < NB; b++) atomicAdd(&s_h[b], (double)wl[b]);
    }
    __syncthreads();
    if (threadIdx.x < NB) atomicAdd(&d_hpwl[threadIdx.x], s_h[threadIdx.x]);
}

// ---------------- congestion: split-K rank-1 accumulation GEMM ----------------
// Block = one padded net-group (176 nets, 22 chunks of 8), all 4 batches
// (64 threads each), thread tile 8x8 (1.0 B/FMA). Ping-pong smem + MANUAL
// register prefetch: k+1's 4 float4 loads issue before k's 32 FFMA2, hiding
// the 29-cyc LDS latency and overlapping the LDS floor with the FMA floor.
union F4U { float4 f; unsigned long long u[2]; };

__device__ __forceinline__ void cong_fill(
    float (&s_x)[2][NB][NKC][GRID], float (&s_y)[2][NB][NKC][GRID],
    int buf, int base, int tid)
{
#pragma unroll
    for (int it0 = 0; it0 < 2; it0++) {          // NKC*64 = 512 items / 256 thr
        int it  = it0 * 256 + tid;
        int k   = it >> 6;
        int bi  = (it >> 4) & 3;
        int sub = it & 15;
        int a   = sub >> 3;          // 0 = x axis, 1 = y axis
        int g0  = (sub & 7) * 8;     // 8 cells per item
        float4 bb = __ldg((const float4*)d_bbox + (base + k) * NB + bi);
        float lmn = a ? bb.z : bb.x;
        float lmx = a ? bb.w : bb.y;
        float u   = __expf(2.f * (lmn - (float)g0) - 1.f);
        float vv  = __expf(2.f * ((float)g0 - lmx) - 1.f);
        float Cc  = __expf(-2.f * (lmx - lmn + 1.f));
        float base1 = 1.f + Cc;
        float scale = 1.f;
        if (a) {
            float bs = fmaxf((bb.y - bb.x + 1.f) * (bb.w - bb.z + 1.f), 1.f);
            scale = __fdividef(1.f, bs);
        }
        float* dst = a ? &s_y[buf][bi][k][g0] : &s_x[buf][bi][k][g0];
#pragma unroll
        for (int g = 0; g < 8; g++) {
            dst[g] = __fdividef(scale, base1 + u + vv);  // sigmoid product (y: /bbox_size)
            u  *= 0.13533528323661270f;                  // e^-2
            vv *= 7.3890560989306495f;                   // e^+2
        }
    }
}

__global__ __launch_bounds__(256, 2) void k_cong() {
    __shared__ float s_x[2][NB][NKC][GRID];     // 16 KB
    __shared__ float s_y[2][NB][NKC][GRID];     // 16 KB
    int tid   = threadIdx.x;
    int group = blockIdx.x;
    int b     = tid >> 6;           // batch (0..3)
    int t64   = tid & 63;
    int j0    = (t64 & 7) * 8;      // x-columns
    int i0    = (t64 >> 3) * 8;     // y-rows
    int n0    = group * NPER;

    unsigned long long acc[8][4];   // acc[i][jp]: row i0+i, col pair (j0+2jp, +1)
#pragma unroll
    for (int i = 0; i < 8; i++)
#pragma unroll
        for (int jp = 0; jp < 4; jp++) acc[i][jp] = 0ull;

    cong_fill(s_x, s_y, 0, n0, tid);
    __syncthreads();

    const int NCHUNK = NPER / NKC;              // 22
    for (int c = 0; c < NCHUNK; c++) {
        int cur = c & 1;
        // software pipeline: prefetch k+1 while FMA'ing k
        F4U cx0, cx1, cy0, cy1;
        cx0.f = *(const float4*)&s_x[cur][b][0][j0];
        cx1.f = *(const float4*)&s_x[cur][b][0][j0 + 4];
        cy0.f = *(const float4*)&s_y[cur][b][0][i0];
        cy1.f = *(const float4*)&s_y[cur][b][0][i0 + 4];
#pragma unroll
        for (int k = 0; k < NKC; k++) {
            F4U nx0, nx1, ny0, ny1;
            if (k + 1 < NKC) {
                nx0.f = *(const float4*)&s_x[cur][b][k + 1][j0];
                nx1.f = *(const float4*)&s_x[cur][b][k + 1][j0 + 4];
                ny0.f = *(const float4*)&s_y[cur][b][k + 1][i0];
                ny1.f = *(const float4*)&s_y[cur][b][k + 1][i0 + 4];
            }
            float yv[8] = {cy0.f.x, cy0.f.y, cy0.f.z, cy0.f.w,
                           cy1.f.x, cy1.f.y, cy1.f.z, cy1.f.w};
#pragma unroll
            for (int i = 0; i < 8; i++) {
                unsigned long long yy;
                asm("mov.b64 %0, {%1, %1};" : "=l"(yy) : "f"(yv[i]));
                asm("fma.rn.f32x2 %0, %1, %2, %0;" : "+l"(acc[i][0]) : "l"(yy), "l"(cx0.u[0]));
                asm("fma.rn.f32x2 %0, %1, %2, %0;" : "+l"(acc[i][1]) : "l"(yy), "l"(cx0.u[1]));
                asm("fma.rn.f32x2 %0, %1, %2, %0;" : "+l"(acc[i][2]) : "l"(yy), "l"(cx1.u[0]));
                asm("fma.rn.f32x2 %0, %1, %2, %0;" : "+l"(acc[i][3]) : "l"(yy), "l"(cx1.u[1]));
            }
            if (k + 1 < NKC) { cx0 = nx0; cx1 = nx1; cy0 = ny0; cy1 = ny1; }
        }
        if (c + 1 < NCHUNK)
            cong_fill(s_x, s_y, cur ^ 1, n0 + (c + 1) * NKC, tid);
        __syncthreads();   // ends chunk: next fill may then overwrite 'cur'
    }

    // atomic-free epilogue: exclusive partial slab per group
    float* dst = &d_part[((size_t)group * NB + b) * (GRID * GRID) + i0 * GRID + j0];
#pragma unroll
    for (int i = 0; i < 8; i++) {
        F4U lo, hi;
        lo.u[0] = acc[i][0]; lo.u[1] = acc[i][1];
        hi.u[0] = acc[i][2]; hi.u[1] = acc[i][3];
        *(float4*)(dst + i * GRID)     = lo.f;
        *(float4*)(dst + i * GRID + 4) = hi.f;
    }
}

// ---------------- reduce group partials -> d_rudy ----------------
// 512 blocks, 8 threads per cell (296 = 8 x 37): 37-deep chains, high MLP.
__global__ __launch_bounds__(256) void k_reduce() {
    int t    = threadIdx.x;
    int cell = blockIdx.x * 32 + (t >> 3);      // 512 blocks x 32 cells
    int part = t & 7;
    const float* p = d_part + cell;
    float s = 0.f;
    int g0 = part * (NGRP / 8);                 // 37 groups per part
#pragma unroll
    for (int g = g0; g < g0 + NGRP / 8; g++) s += p[(size_t)g * (NB * GRID * GRID)];
    s += __shfl_xor_sync(0xffffffffu, s, 1);
    s += __shfl_xor_sync(0xffffffffu, s, 2);
    s += __shfl_xor_sync(0xffffffffu, s, 4);
    if (part == 0) d_rudy[cell] = s;
}

// ---------------- separable Gaussian smooth + overflow penalty + final ----------------
__global__ __launch_bounds__(256) void k_final(float* __restrict__ out) {
    int b = blockIdx.x;
    __shared__ float s_in[GRID][GRID];
    __shared__ float s_tmp[GRID][GRID];
    __shared__ float s_red[256];
    int tid = threadIdx.x;

    float w[7];
    {
        float sum = 0.f;
#pragma unroll
        for (int i = 0; i < 7; i++) {
            float x = (float)(i - 3);
            w[i] = expf(-x * x / 4.5f);   // 2*sigma^2 = 4.5
            sum += w[i];
        }
        float inv = 1.f / sum;
#pragma unroll
        for (int i = 0; i < 7; i++) w[i] *= inv;  // outer(w,w) == normalized 2D kernel
    }

    for (int i = tid; i < GRID * GRID; i += 256)
        s_in[i >> 6][i & 63] = d_rudy[b * GRID * GRID + i];
    __syncthreads();

    for (int i = tid; i < GRID * GRID; i += 256) {
        int r = i >> 6, cx = i & 63;
        float acc = 0.f;
#pragma unroll
        for (int d = -3; d <= 3; d++) {
            int rr = r + d;
            if (rr >= 0 && rr < GRID) acc = fmaf(w[d + 3], s_in[rr][cx], acc);
        }
        s_tmp[r][cx] = acc;
    }
    __syncthreads();

    float pen = 0.f;
    for (int i = tid; i < GRID * GRID; i += 256) {
        int r = i >> 6, cx = i & 63;
        float acc = 0.f;
#pragma unroll
        for (int d = -3; d <= 3; d++) {
            int cc = cx + d;
            if (cc >= 0 && cc < GRID) acc = fmaf(w[d + 3], s_tmp[r][cc], acc);
        }
        float o = acc - 1.f;            // THRESH = 1
        if (o > 0.f) pen = fmaf(o, o, pen);
    }
    s_red[tid] = pen;
    __syncthreads();
    for (int s = 128; s > 0; s >>= 1) {
        if (tid < s) s_red[tid] += s_red[tid + s];
        __syncthreads();
    }
    if (tid == 0)
        out[b] = (float)(d_hpwl[b] + 0.5 * (double)s_red[0]);  // W_WL=1, W_CONG=0.5
}

// ---------------- launcher ----------------
extern "C" void kernel_launch(void* const* d_in, const int* in_sizes, int n_in,
                              void* d_out, int out_size)
{
    const float* positions = nullptr;
    const int*   n2p = nullptr;
    const int*   p2m = nullptr;
    const float* poff = nullptr;
    const float* roh = nullptr;
    const float* nw = nullptr;

    for (int i = 0; i < n_in; i++) {
        switch (in_sizes[i]) {                      // all element counts distinct
            case NB * NV * 2:    positions = (const float*)d_in[i]; break; // 160000
            case NNETS * MPINS:  n2p       = (const int*)  d_in[i]; break; // 1600000
            case NP:             p2m       = (const int*)  d_in[i]; break; // 400000
            case NP * 2:         poff      = (const float*)d_in[i]; break; // 800000
            case NB * NV * 4:    roh       = (const float*)d_in[i]; break; // 320000
            case NNETS:          nw        = (const float*)d_in[i]; break; // 50000
            default: break;
        }
    }
    if (!positions || !n2p || !p2m || !poff || !roh || !nw) return;

    k_pinpos<<<PPB + 33, 256>>>(positions, roh, p2m, poff);   // tail blocks do init
    k_net<<<(NNETS + 31) / 32, 256>>>(n2p, nw);
    k_cong<<<NGRP, 256>>>();
    k_reduce<<<512, 256>>>();
    k_final<<<NB, 256>>>((float*)d_out);
}

// round 17
// speedup vs baseline: 1.6296x; 1.0406x over previous
#include <cuda_runtime.h>
#include <cstdint>

#define NB 4
#define NV 20000
#define NP 400000
#define NNETS 50000
#define MPINS 32
#define GRID 64

#define NKC 8           // nets per smem stage (per buffer)
#define NGRP 296        // k_cong blocks = net groups (2 CTAs/SM)
#define NPER 176        // padded nets per group (22 chunks of 8)
#define NNP (NGRP * NPER)   // 52096 padded nets
#define PPB ((NP + 255) / 256)   // 1563 pinpos blocks

// -------- static scratch (no allocation allowed) --------
__device__ float4 d_posrot[NB * NV];            // packed (pos.x, pos.y, c, s) per (b, macro)
__device__ float  d_pin_pos[NP * 8];            // [P][B][2] -> 2x float4 per pin
__device__ float  d_bbox[NNP * NB * 4];         // per (net,batch): xmin,xmax,ymin,ymax (grid units)
__device__ float  d_part[NGRP * NB * GRID * GRID];  // per-group rudy partials (19.4 MB)
__device__ float  d_rudy[NB * GRID * GRID];
__device__ double d_hpwl[NB];

// ---------------- pack positions + rotation (coalesced, tiny) --------------
__global__ __launch_bounds__(256) void k_pack(
    const float* __restrict__ pos,   // (B,V,2)
    const float* __restrict__ roh)   // (B,V,4)
{
    int i = blockIdx.x * blockDim.x + threadIdx.x;   // (b*NV + m)
    if (i >= NB * NV) return;
    float2 mp = ((const float2*)pos)[i];
    float4 oh = ((const float4*)roh)[i];
    // rotations 0..3 collapse to cos/sin in {-1,0,1}
    d_posrot[i] = make_float4(mp.x, mp.y, oh.x - oh.z, oh.y - oh.w);
}

// ---------------- pin positions (+ folded init in tail blocks) -------------
// 4 gathers per pin (was 8): one packed float4 per batch.
__global__ __launch_bounds__(256) void k_pinpos(
    const int*   __restrict__ p2m,   // (P,)
    const float* __restrict__ poff)  // (P,2)
{
    if (blockIdx.x >= PPB) {   // init tail: sentinels for padded nets + hpwl zero
        int t = (blockIdx.x - PPB) * 256 + threadIdx.x;
        if (t < (NNP - NNETS) * NB)   // sentinel -> denom=inf -> window == 0
            ((float4*)d_bbox)[NNETS * NB + t] = make_float4(2000.f, -2000.f, 2000.f, -2000.f);
        if (t < NB) d_hpwl[t] = 0.0;
        return;
    }
    int p = blockIdx.x * blockDim.x + threadIdx.x;
    if (p >= NP) return;
    int m = p2m[p];
    float2 off = ((const float2*)poff)[p];
    float o[8];
#pragma unroll
    for (int b = 0; b < NB; b++) {
        float4 pr = __ldg(&d_posrot[b * NV + m]);   // (px, py, c, s)
        o[2 * b + 0] = pr.x + pr.z * off.x - pr.w * off.y;
        o[2 * b + 1] = pr.y + pr.w * off.x + pr.z * off.y;
    }
    float4* dst = (float4*)d_pin_pos + p * 2;
    dst[0] = make_float4(o[0], o[1], o[2], o[3]);
    dst[1] = make_float4(o[4], o[5], o[6], o[7]);
}

// ---------------- per-net LSE wirelength + bbox ----------------
// 4 nets per warp: 8 lanes per net, 4 pin slots per lane. Guarded loads
// (branchless variant measured +60us — do not revisit).
__global__ __launch_bounds__(256) void k_net(
    const int*   __restrict__ n2p,   // (NN,32)
    const float* __restrict__ nw)    // (NN,)
{
    int warpG = (blockIdx.x * blockDim.x + threadIdx.x) >> 5;
    int lane  = threadIdx.x & 31;
    int grp   = lane >> 3;           // net slot within warp (0..3)
    int r     = lane & 7;            // lane within group
    int net   = warpG * 4 + grp;
    bool act  = (net < NNETS);

    float mx[NB][2], mn[NB][2], s1[NB][2], s2[NB][2];
#pragma unroll
    for (int b = 0; b < NB; b++)
#pragma unroll
        for (int a = 0; a < 2; a++) {
            mx[b][a] = -1e9f; mn[b][a] = 1e9f;
            s1[b][a] = 0.f;   s2[b][a] = 0.f;
        }

    if (act) {
        int4 idx4 = __ldg((const int4*)n2p + net * 8 + r);
        int idxs[4] = {idx4.x, idx4.y, idx4.z, idx4.w};
#pragma unroll
        for (int s = 0; s < 4; s++) {
            int idx = idxs[s];
            if (idx >= 0) {
                const float4* pp = (const float4*)d_pin_pos + (size_t)idx * 2;
                float4 lo = __ldg(pp), hi = __ldg(pp + 1);
                float v[NB][2] = {{lo.x, lo.y}, {lo.z, lo.w}, {hi.x, hi.y}, {hi.z, hi.w}};
#pragma unroll
                for (int b = 0; b < NB; b++)
#pragma unroll
                    for (int a = 0; a < 2; a++) {
                        float val = v[b][a];
                        mx[b][a] = fmaxf(mx[b][a], val);
                        mn[b][a] = fminf(mn[b][a], val);
                        // masked slots contribute exactly 0; |v|<=1 -> bounded
                        s1[b][a] += __expf( 10.f * val);
                        s2[b][a] += __expf(-10.f * val);
                    }
            }
        }
    }

    // 3-step butterfly within each 8-lane group (xor 4,2,1 stay in-group)
#pragma unroll
    for (int o = 4; o > 0; o >>= 1) {
#pragma unroll
        for (int b = 0; b < NB; b++)
#pragma unroll
            for (int a = 0; a < 2; a++) {
                mx[b][a] = fmaxf(mx[b][a], __shfl_xor_sync(0xffffffffu, mx[b][a], o));
                mn[b][a] = fminf(mn[b][a], __shfl_xor_sync(0xffffffffu, mn[b][a], o));
                s1[b][a] += __shfl_xor_sync(0xffffffffu, s1[b][a], o);
                s2[b][a] += __shfl_xor_sync(0xffffffffu, s2[b][a], o);
            }
    }

    float wl[NB] = {0.f, 0.f, 0.f, 0.f};
    if (r == 0 && act) {
        float w = __ldg(&nw[net]);
#pragma unroll
        for (int b = 0; b < NB; b++) {
            // (lse_max - lse_min) over both axes == 0.1 * log(S1x*S2x*S1y*S2y)
            float prod = (s1[b][0] * s2[b][0]) * (s1[b][1] * s2[b][1]);
            wl[b] = w * 0.1f * __logf(prod);
            float4 bb;
            bb.x = (mn[b][0] + 1.f) * 31.5f;   // (M-1)/2
            bb.y = (mx[b][0] + 1.f) * 31.5f;
            bb.z = (mn[b][1] + 1.f) * 31.5f;
            bb.w = (mx[b][1] + 1.f) * 31.5f;
            ((float4*)d_bbox)[net * NB + b] = bb;
        }
    }
#pragma unroll
    for (int b = 0; b < NB; b++) {
        wl[b] += __shfl_xor_sync(0xffffffffu, wl[b], 8);
        wl[b] += __shfl_xor_sync(0xffffffffu, wl[b], 16);
    }

    __shared__ double s_h[NB];
    if (threadIdx.x < NB) s_h[threadIdx.x] = 0.0;
    __syncthreads();
    if (lane == 0) {
#pragma unroll
        for (int b = 0; b < NB; b++) atomicAdd(&s_h[b], (double)wl[b]);
    }
    __syncthreads();
    if (threadIdx.x < NB) atomicAdd(&d_hpwl[threadIdx.x], s_h[threadIdx.x]);
}

// ---------------- congestion: split-K rank-1 accumulation GEMM ----------------
// Block = one padded net-group (176 nets, 22 chunks of 8), all 4 batches
// (64 threads each), thread tile 8x8 (1.0 B/FMA). Ping-pong smem + MANUAL
// register prefetch: k+1's 4 float4 loads issue before k's 32 FFMA2, hiding
// the 29-cyc LDS latency and overlapping the LDS floor with the FMA floor.
union F4U { float4 f; unsigned long long u[2]; };

__device__ __forceinline__ void cong_fill(
    float (&s_x)[2][NB][NKC][GRID], float (&s_y)[2][NB][NKC][GRID],
    int buf, int base, int tid)
{
#pragma unroll
    for (int it0 = 0; it0 < 2; it0++) {          // NKC*64 = 512 items / 256 thr
        int it  = it0 * 256 + tid;
        int k   = it >> 6;
        int bi  = (it >> 4) & 3;
        int sub = it & 15;
        int a   = sub >> 3;          // 0 = x axis, 1 = y axis
        int g0  = (sub & 7) * 8;     // 8 cells per item
        float4 bb = __ldg((const float4*)d_bbox + (base + k) * NB + bi);
        float lmn = a ? bb.z : bb.x;
        float lmx = a ? bb.w : bb.y;
        float u   = __expf(2.f * (lmn - (float)g0) - 1.f);
        float vv  = __expf(2.f * ((float)g0 - lmx) - 1.f);
        float Cc  = __expf(-2.f * (lmx - lmn + 1.f));
        float base1 = 1.f + Cc;
        float scale = 1.f;
        if (a) {
            float bs = fmaxf((bb.y - bb.x + 1.f) * (bb.w - bb.z + 1.f), 1.f);
            scale = __fdividef(1.f, bs);
        }
        float* dst = a ? &s_y[buf][bi][k][g0] : &s_x[buf][bi][k][g0];
#pragma unroll
        for (int g = 0; g < 8; g++) {
            dst[g] = __fdividef(scale, base1 + u + vv);  // sigmoid product (y: /bbox_size)
            u  *= 0.13533528323661270f;                  // e^-2
            vv *= 7.3890560989306495f;                   // e^+2
        }
    }
}

__global__ __launch_bounds__(256, 2) void k_cong() {
    __shared__ float s_x[2][NB][NKC][GRID];     // 16 KB
    __shared__ float s_y[2][NB][NKC][GRID];     // 16 KB
    int tid   = threadIdx.x;
    int group = blockIdx.x;
    int b     = tid >> 6;           // batch (0..3)
    int t64   = tid & 63;
    int j0    = (t64 & 7) * 8;      // x-columns
    int i0    = (t64 >> 3) * 8;     // y-rows
    int n0    = group * NPER;

    unsigned long long acc[8][4];   // acc[i][jp]: row i0+i, col pair (j0+2jp, +1)
#pragma unroll
    for (int i = 0; i < 8; i++)
#pragma unroll
        for (int jp = 0; jp < 4; jp++) acc[i][jp] = 0ull;

    cong_fill(s_x, s_y, 0, n0, tid);
    __syncthreads();

    const int NCHUNK = NPER / NKC;              // 22
    for (int c = 0; c < NCHUNK; c++) {
        int cur = c & 1;
        // software pipeline: prefetch k+1 while FMA'ing k
        F4U cx0, cx1, cy0, cy1;
        cx0.f = *(const float4*)&s_x[cur][b][0][j0];
        cx1.f = *(const float4*)&s_x[cur][b][0][j0 + 4];
        cy0.f = *(const float4*)&s_y[cur][b][0][i0];
        cy1.f = *(const float4*)&s_y[cur][b][0][i0 + 4];
#pragma unroll
        for (int k = 0; k < NKC; k++) {
            F4U nx0, nx1, ny0, ny1;
            if (k + 1 < NKC) {
                nx0.f = *(const float4*)&s_x[cur][b][k + 1][j0];
                nx1.f = *(const float4*)&s_x[cur][b][k + 1][j0 + 4];
                ny0.f = *(const float4*)&s_y[cur][b][k + 1][i0];
                ny1.f = *(const float4*)&s_y[cur][b][k + 1][i0 + 4];
            }
            float yv[8] = {cy0.f.x, cy0.f.y, cy0.f.z, cy0.f.w,
                           cy1.f.x, cy1.f.y, cy1.f.z, cy1.f.w};
#pragma unroll
            for (int i = 0; i < 8; i++) {
                unsigned long long yy;
                asm("mov.b64 %0, {%1, %1};" : "=l"(yy) : "f"(yv[i]));
                asm("fma.rn.f32x2 %0, %1, %2, %0;" : "+l"(acc[i][0]) : "l"(yy), "l"(cx0.u[0]));
                asm("fma.rn.f32x2 %0, %1, %2, %0;" : "+l"(acc[i][1]) : "l"(yy), "l"(cx0.u[1]));
                asm("fma.rn.f32x2 %0, %1, %2, %0;" : "+l"(acc[i][2]) : "l"(yy), "l"(cx1.u[0]));
                asm("fma.rn.f32x2 %0, %1, %2, %0;" : "+l"(acc[i][3]) : "l"(yy), "l"(cx1.u[1]));
            }
            if (k + 1 < NKC) { cx0 = nx0; cx1 = nx1; cy0 = ny0; cy1 = ny1; }
        }
        if (c + 1 < NCHUNK)
            cong_fill(s_x, s_y, cur ^ 1, n0 + (c + 1) * NKC, tid);
        __syncthreads();   // ends chunk: next fill may then overwrite 'cur'
    }

    // atomic-free epilogue: exclusive partial slab per group
    float* dst = &d_part[((size_t)group * NB + b) * (GRID * GRID) + i0 * GRID + j0];
#pragma unroll
    for (int i = 0; i < 8; i++) {
        F4U lo, hi;
        lo.u[0] = acc[i][0]; lo.u[1] = acc[i][1];
        hi.u[0] = acc[i][2]; hi.u[1] = acc[i][3];
        *(float4*)(dst + i * GRID)     = lo.f;
        *(float4*)(dst + i * GRID + 4) = hi.f;
    }
}

// ---------------- reduce group partials -> d_rudy ----------------
// float4 per thread (4 cells), 8 parts per cell-quad: 37-deep float4 chains,
// 4x fewer load instructions for the same bytes.
__global__ __launch_bounds__(256) void k_reduce() {
    int t    = threadIdx.x;
    int quad = blockIdx.x * 32 + (t >> 3);      // 128 blocks x 32 quads = 4096
    int part = t & 7;
    const float4* p = (const float4*)d_part + quad;
    float4 s = make_float4(0.f, 0.f, 0.f, 0.f);
    int g0 = part * (NGRP / 8);                 // 37 groups per part
#pragma unroll
    for (int g = g0; g < g0 + NGRP / 8; g++) {
        float4 v = p[(size_t)g * (NB * GRID * GRID / 4)];
        s.x += v.x; s.y += v.y; s.z += v.z; s.w += v.w;
    }
#pragma unroll
    for (int o = 1; o < 8; o <<= 1) {
        s.x += __shfl_xor_sync(0xffffffffu, s.x, o);
        s.y += __shfl_xor_sync(0xffffffffu, s.y, o);
        s.z += __shfl_xor_sync(0xffffffffu, s.z, o);
        s.w += __shfl_xor_sync(0xffffffffu, s.w, o);
    }
    if (part == 0) ((float4*)d_rudy)[quad] = s;
}

// ---------------- separable Gaussian smooth + overflow penalty + final ----------------
__global__ __launch_bounds__(256) void k_final(float* __restrict__ out) {
    int b = blockIdx.x;
    __shared__ float s_in[GRID][GRID];
    __shared__ float s_tmp[GRID][GRID];
    __shared__ float s_red[256];
    int tid = threadIdx.x;

    float w[7];
    {
        float sum = 0.f;
#pragma unroll
        for (int i = 0; i < 7; i++) {
            float x = (float)(i - 3);
            w[i] = expf(-x * x / 4.5f);   // 2*sigma^2 = 4.5
            sum += w[i];
        }
        float inv = 1.f / sum;
#pragma unroll
        for (int i = 0; i < 7; i++) w[i] *= inv;  // outer(w,w) == normalized 2D kernel
    }

    for (int i = tid; i < GRID * GRID; i += 256)
        s_in[i >> 6][i & 63] = d_rudy[b * GRID * GRID + i];
    __syncthreads();

    for (int i = tid; i < GRID * GRID; i += 256) {
        int r = i >> 6, cx = i & 63;
        float acc = 0.f;
#pragma unroll
        for (int d = -3; d <= 3; d++) {
            int rr = r + d;
            if (rr >= 0 && rr < GRID) acc = fmaf(w[d + 3], s_in[rr][cx], acc);
        }
        s_tmp[r][cx] = acc;
    }
    __syncthreads();

    float pen = 0.f;
    for (int i = tid; i < GRID * GRID; i += 256) {
        int r = i >> 6, cx = i & 63;
        float acc = 0.f;
#pragma unroll
        for (int d = -3; d <= 3; d++) {
            int cc = cx + d;
            if (cc >= 0 && cc < GRID) acc = fmaf(w[d + 3], s_tmp[r][cc], acc);
        }
        float o = acc - 1.f;            // THRESH = 1
        if (o > 0.f) pen = fmaf(o, o, pen);
    }
    s_red[tid] = pen;
    __syncthreads();
    for (int s = 128; s > 0; s >>= 1) {
        if (tid < s) s_red[tid] += s_red[tid + s];
        __syncthreads();
    }
    if (tid == 0)
        out[b] = (float)(d_hpwl[b] + 0.5 * (double)s_red[0]);  // W_WL=1, W_CONG=0.5
}

// ---------------- launcher ----------------
extern "C" void kernel_launch(void* const* d_in, const int* in_sizes, int n_in,
                              void* d_out, int out_size)
{
    const float* positions = nullptr;
    const int*   n2p = nullptr;
    const int*   p2m = nullptr;
    const float* poff = nullptr;
    const float* roh = nullptr;
    const float* nw = nullptr;

    for (int i = 0; i < n_in; i++) {
        switch (in_sizes[i]) {                      // all element counts distinct
            case NB * NV * 2:    positions = (const float*)d_in[i]; break; // 160000
            case NNETS * MPINS:  n2p       = (const int*)  d_in[i]; break; // 1600000
            case NP:             p2m       = (const int*)  d_in[i]; break; // 400000
            case NP * 2:         poff      = (const float*)d_in[i]; break; // 800000
            case NB * NV * 4:    roh       = (const float*)d_in[i]; break; // 320000
            case NNETS:          nw        = (const float*)d_in[i]; break; // 50000
            default: break;
        }
    }
    if (!positions || !n2p || !p2m || !poff || !roh || !nw) return;

    k_pack<<<(NB * NV + 255) / 256, 256>>>(positions, roh);
    k_pinpos<<<PPB + 33, 256>>>(p2m, poff);   // tail blocks do init
    k_net<<<(NNETS + 31) / 32, 256>>>(n2p, nw);
    k_cong<<<NGRP, 256>>>();
    k_reduce<<<128, 256>>>();
    k_final<<<NB, 256>>>((float*)d_out);
}